// round 15
// baseline (speedup 1.0000x reference)
#include <cuda_runtime.h>
#include <cuda_fp16.h>
#include <math.h>
#include <stdint.h>

#define HID 1024
#define NE 3
#define DI 1280
#define D2 2560
#define NB 4
#define SEQ 4096
#define EPSV 1e-6f
#define NCH 64
#define CH  64

// ---------------- scratch (device globals) ----------------
__device__ __half g_xnh[(size_t)NB * SEQ * HID];
__device__ float g_partial[NB * 128 * HID];
__device__ float g_probs[NB * NE];
__device__ __half g_WiT[(size_t)NB * HID * D2];   // hid/gate interleaved rows
__device__ float g_bi[NB * D2];
__device__ __half g_WoT[(size_t)NB * DI * HID];
__device__ float g_bo[NB * HID];
__device__ __half2 g_aw[(size_t)NB * SEQ * DI];
__device__ __half g_hs[(size_t)NB * SEQ * DI];
__device__ float g_cA[NB * NCH * DI];
__device__ float g_cW[NB * NCH * DI];
__device__ float g_h0[NB * NCH * DI];

// ---------------- PTX helpers ----------------
__device__ __forceinline__ uint32_t smem_u32(const void* p) {
    uint32_t a;
    asm("{ .reg .u64 t; cvta.to.shared.u64 t, %1; cvt.u32.u64 %0, t; }" : "=r"(a) : "l"(p));
    return a;
}
__device__ __forceinline__ void cpa16(uint32_t dst, const void* src) {
    asm volatile("{\n .reg .u64 g;\n cvta.to.global.u64 g, %1;\n"
                 " cp.async.cg.shared.global [%0], [g], 16;\n}"
                 :: "r"(dst), "l"(src));
}
__device__ __forceinline__ void ldsm_x4(uint32_t& r0, uint32_t& r1, uint32_t& r2, uint32_t& r3,
                                        uint32_t addr) {
    asm volatile("ldmatrix.sync.aligned.m8n8.x4.shared.b16 {%0,%1,%2,%3}, [%4];"
                 : "=r"(r0), "=r"(r1), "=r"(r2), "=r"(r3) : "r"(addr));
}
__device__ __forceinline__ void mma_f16(float& d0, float& d1, float& d2, float& d3,
                                        uint32_t a0, uint32_t a1, uint32_t a2, uint32_t a3,
                                        uint32_t b0, uint32_t b1) {
    asm volatile("mma.sync.aligned.m16n8k16.row.col.f32.f16.f16.f32 "
                 "{%0,%1,%2,%3}, {%4,%5,%6,%7}, {%8,%9}, {%0,%1,%2,%3};"
                 : "+f"(d0), "+f"(d1), "+f"(d2), "+f"(d3)
                 : "r"(a0), "r"(a1), "r"(a2), "r"(a3), "r"(b0), "r"(b1));
}
__device__ __forceinline__ void mbar_init(uint32_t a, uint32_t cnt) {
    asm volatile("mbarrier.init.shared.b64 [%0], %1;" :: "r"(a), "r"(cnt) : "memory");
}
__device__ __forceinline__ void mbar_arrive(uint32_t a) {
    asm volatile("mbarrier.arrive.shared.b64 _, [%0];" :: "r"(a) : "memory");
}
__device__ __forceinline__ void cpasync_mbar_arrive_noinc(uint32_t a) {
    asm volatile("cp.async.mbarrier.arrive.noinc.shared.b64 [%0];" :: "r"(a) : "memory");
}
__device__ __forceinline__ void mbar_wait(uint32_t a, uint32_t parity) {
    asm volatile("{\n\t.reg .pred P;\n"
                 "LW%=:\n\tmbarrier.try_wait.parity.acquire.cta.shared::cta.b64 P, [%0], %1, 0x989680;\n"
                 "\t@!P bra LW%=;\n\t}"
                 :: "r"(a), "r"(parity) : "memory");
}

// ---------------- 1. fused RMSNorm -> fp16 + pooled partial ----------------
__global__ __launch_bounds__(256) void norm_pool_kernel(const float* __restrict__ in,
                                                        const float* __restrict__ nw,
                                                        __half* __restrict__ xnh,
                                                        float* __restrict__ partial) {
    __shared__ float sp[8][1024];
    const int blk = blockIdx.x;
    const int b = blk >> 7, ch = blk & 127;
    const int wid = threadIdx.x >> 5, lane = threadIdx.x & 31;

    float4 wv[8];
    #pragma unroll
    for (int i = 0; i < 8; i++) wv[i] = *(const float4*)(nw + i * 128 + lane * 4);

    float4 pacc[8];
    #pragma unroll
    for (int i = 0; i < 8; i++) pacc[i] = make_float4(0.f, 0.f, 0.f, 0.f);

    const long long rowBase = (long long)b * SEQ + ch * 32 + wid * 4;
    #pragma unroll
    for (int r = 0; r < 4; r++) {
        const float* rp = in + (rowBase + r) * HID;
        float4 v[8];
        float ss = 0.f;
        #pragma unroll
        for (int i = 0; i < 8; i++) {
            v[i] = *(const float4*)(rp + i * 128 + lane * 4);
            ss += v[i].x * v[i].x + v[i].y * v[i].y + v[i].z * v[i].z + v[i].w * v[i].w;
        }
        #pragma unroll
        for (int o = 16; o > 0; o >>= 1) ss += __shfl_xor_sync(0xffffffffu, ss, o);
        float scale = rsqrtf(ss * (1.0f / HID) + EPSV);
        __half* op = xnh + (rowBase + r) * HID;
        #pragma unroll
        for (int i = 0; i < 8; i++) {
            float x0 = v[i].x * scale * wv[i].x;
            float x1 = v[i].y * scale * wv[i].y;
            float x2 = v[i].z * scale * wv[i].z;
            float x3 = v[i].w * scale * wv[i].w;
            pacc[i].x += x0; pacc[i].y += x1; pacc[i].z += x2; pacc[i].w += x3;
            __half2 p0 = __floats2half2_rn(x0, x1);
            __half2 p1 = __floats2half2_rn(x2, x3);
            uint2 u;
            u.x = *(uint32_t*)&p0;
            u.y = *(uint32_t*)&p1;
            *(uint2*)(op + i * 128 + lane * 4) = u;
        }
    }
    #pragma unroll
    for (int i = 0; i < 8; i++) *(float4*)(&sp[wid][i * 128 + lane * 4]) = pacc[i];
    __syncthreads();
    float* pp = partial + (long long)(b * 128 + ch) * HID;
    int h = threadIdx.x * 4;
    float4 s = make_float4(0.f, 0.f, 0.f, 0.f);
    #pragma unroll
    for (int w = 0; w < 8; w++) {
        float4 q = *(float4*)(&sp[w][h]);
        s.x += q.x; s.y += q.y; s.z += q.z; s.w += q.w;
    }
    *(float4*)(pp + h) = s;
}

// ---------------- 2. router (one block per batch) ----------------
__global__ void router_kernel(const float* __restrict__ partial,
                              const float* __restrict__ rw,
                              const float* __restrict__ rb,
                              float* __restrict__ probs) {
    __shared__ float red[3][32];
    const int b = blockIdx.x;
    const int h = threadIdx.x;
    const int wid = h >> 5, lid = h & 31;
    float s = 0.f;
    #pragma unroll 16
    for (int c = 0; c < 128; c++) s += partial[(long long)(b * 128 + c) * HID + h];
    float p = s * (1.0f / SEQ);
    float a0 = p * rw[h * NE + 0];
    float a1 = p * rw[h * NE + 1];
    float a2 = p * rw[h * NE + 2];
    #pragma unroll
    for (int o = 16; o > 0; o >>= 1) {
        a0 += __shfl_xor_sync(0xffffffffu, a0, o);
        a1 += __shfl_xor_sync(0xffffffffu, a1, o);
        a2 += __shfl_xor_sync(0xffffffffu, a2, o);
    }
    if (lid == 0) { red[0][wid] = a0; red[1][wid] = a1; red[2][wid] = a2; }
    __syncthreads();
    if (h == 0) {
        float l0 = rb[0], l1 = rb[1], l2 = rb[2];
        #pragma unroll
        for (int w = 0; w < 32; w++) { l0 += red[0][w]; l1 += red[1][w]; l2 += red[2][w]; }
        float mx = fmaxf(l0, fmaxf(l1, l2));
        float e0 = expf(l0 - mx), e1 = expf(l1 - mx), e2 = expf(l2 - mx);
        float inv = 1.0f / (e0 + e1 + e2);
        probs[b * 3 + 0] = e0 * inv;
        probs[b * 3 + 1] = e1 * inv;
        probs[b * 3 + 2] = e2 * inv;
    }
}

// ---------------- 3. fused mixing (half2 stores) ----------------
__device__ __forceinline__ void mixT_body(__half* __restrict__ dst,
                                          const float* __restrict__ src,
                                          const float* __restrict__ probs,
                                          int K, int N, int bx, int by, int tid, int perm) {
    __shared__ float t0[32][33], t1[32][33], t2[32][33];
    int tx = tid & 31, ty = tid >> 5;
    int k0 = by * 32, n0 = bx * 32;
    long long eSz = (long long)K * N;
    #pragma unroll
    for (int i = 0; i < 4; i++) {
        int k = k0 + ty + i * 8;
        long long o = (long long)k * N + n0 + tx;
        t0[ty + i * 8][tx] = src[o];
        t1[ty + i * 8][tx] = src[eSz + o];
        t2[ty + i * 8][tx] = src[2 * eSz + o];
    }
    __syncthreads();
    int kp = tid & 15;
    int nOff = tid >> 4;
    #pragma unroll
    for (int b = 0; b < NB; b++) {
        float p0 = probs[b * 3 + 0], p1 = probs[b * 3 + 1], p2 = probs[b * 3 + 2];
        #pragma unroll
        for (int i = 0; i < 2; i++) {
            int n = n0 + nOff + i * 16;
            int nl = nOff + i * 16;
            float va = p0 * t0[2 * kp][nl] + p1 * t1[2 * kp][nl] + p2 * t2[2 * kp][nl];
            float vb = p0 * t0[2 * kp + 1][nl] + p1 * t1[2 * kp + 1][nl] + p2 * t2[2 * kp + 1][nl];
            long long r = perm ? ((n < DI) ? 2 * n : 2 * (n - DI) + 1) : n;
            __half2 hv = __floats2half2_rn(va, vb);
            *(uint32_t*)(dst + (long long)b * eSz + r * K + k0 + 2 * kp) = *(uint32_t*)&hv;
        }
    }
}

__global__ void mix_all_kernel(__half* __restrict__ WiT, __half* __restrict__ WoT,
                               float* __restrict__ bi, float* __restrict__ bo,
                               const float* __restrict__ w_in, const float* __restrict__ w_out,
                               const float* __restrict__ b_in, const float* __restrict__ b_out,
                               const float* __restrict__ probs) {
    int bid = blockIdx.x, tid = threadIdx.x;
    if (bid < 2560) {
        mixT_body(WiT, w_in, probs, HID, D2, bid % 80, bid / 80, tid, 1);
    } else if (bid < 3840) {
        int id = bid - 2560;
        mixT_body(WoT, w_out, probs, DI, HID, id % 32, id / 32, tid, 0);
    } else if (bid < 3880) {
        int i = (bid - 3840) * 256 + tid;
        if (i < NB * D2) {
            int b = i / D2, j = i - b * D2;
            float v = probs[b * 3 + 0] * b_in[j] + probs[b * 3 + 1] * b_in[D2 + j] +
                      probs[b * 3 + 2] * b_in[2 * D2 + j];
            long long r = (j < DI) ? 2 * j : 2 * (j - DI) + 1;
            bi[(long long)b * D2 + r] = v;
        }
    } else {
        int i = (bid - 3880) * 256 + tid;
        if (i < NB * HID) {
            int b = i / HID, j = i - b * HID;
            bo[i] = probs[b * 3 + 0] * b_out[j] + probs[b * 3 + 1] * b_out[HID + j] +
                    probs[b * 3 + 2] * b_out[2 * HID + j];
        }
    }
}

// ---------------- 4/7. fp16 GEMM: mbarrier-decoupled cp.async 3-stage BK=64 ----------------
#define STAGE_BYTES 32768
#define MBAR_OFF (3 * STAGE_BYTES)

__global__ __launch_bounds__(256, 2) void hgemm_kernel(
    const __half* __restrict__ A, const __half* __restrict__ B,
    const float* __restrict__ bias, const float* __restrict__ resid,
    float* __restrict__ C, __half2* __restrict__ awOut,
    float* __restrict__ cA, float* __restrict__ cW, int K, int N,
    long long sA, long long sB, long long sC) {
    extern __shared__ uint8_t dsm[];
    const uint32_t smb = smem_u32(dsm);
    const uint32_t mb = smb + MBAR_OFF;
    const int tid = threadIdx.x;
    const int wid = tid >> 5;
    const int lane = tid & 31;
    const int bb = blockIdx.z;

    const __half* Abase = A + (long long)bb * sA + (long long)blockIdx.y * 128 * K;
    const __half* Bbase = B + (long long)bb * sB + (long long)blockIdx.x * 128 * K;

    const int g = lane >> 2, t = lane & 3;
    const int wm = wid >> 2;
    const int wn = wid & 3;

    float acc[4][4][4];
    #pragma unroll
    for (int i = 0; i < 4; i++)
        #pragma unroll
        for (int j = 0; j < 4; j++)
            #pragma unroll
            for (int q = 0; q < 4; q++) acc[i][j][q] = 0.f;

    const int KT = K >> 6;

    if (tid == 0) {
        #pragma unroll
        for (int s = 0; s < 3; s++) {
            mbar_init(mb + s * 16, 256);
            mbar_init(mb + s * 16 + 8, 256);
        }
    }
    __syncthreads();

    auto issue = [&](int kt, int stg) {
        uint32_t sb = smb + stg * STAGE_BYTES;
        #pragma unroll
        for (int u = 0; u < 4; u++) {
            int c = tid + u * 256;
            int row = c >> 3, k16 = c & 7;
            int phys = k16 ^ (row & 7);
            uint32_t off = row * 128 + phys * 16;
            cpa16(sb + off, Abase + (long long)row * K + kt * 64 + k16 * 8);
            cpa16(sb + 16384 + off, Bbase + (long long)row * K + kt * 64 + k16 * 8);
        }
    };

    #pragma unroll
    for (int k = 0; k < 3; k++) {
        issue(k, k);
        cpasync_mbar_arrive_noinc(mb + k * 16);
    }

    const int mi = lane >> 3;
    const int l7 = lane & 7;

    uint32_t cphBits = 0, pphBits = 0;
    int stC = 0;
    for (int kt = 0; kt < KT; kt++) {
        mbar_wait(mb + stC * 16, (cphBits >> stC) & 1u);
        cphBits ^= (1u << stC);

        uint32_t sa = smb + stC * STAGE_BYTES;
        uint32_t sbm = sa + 16384;
        #pragma unroll
        for (int ks = 0; ks < 4; ks++) {
            uint32_t af[4][4], bf[4][2];
            #pragma unroll
            for (int mf = 0; mf < 4; mf++) {
                int row = wm * 64 + mf * 16 + l7 + (mi & 1) * 8;
                int chunk = 2 * ks + (mi >> 1);
                int phys = chunk ^ (row & 7);
                ldsm_x4(af[mf][0], af[mf][1], af[mf][2], af[mf][3],
                        sa + row * 128 + phys * 16);
            }
            #pragma unroll
            for (int p = 0; p < 2; p++) {
                int row = wn * 32 + p * 16 + l7 + (mi >> 1) * 8;
                int chunk = 2 * ks + (mi & 1);
                int phys = chunk ^ (row & 7);
                uint32_t r0, r1, r2, r3;
                ldsm_x4(r0, r1, r2, r3, sbm + row * 128 + phys * 16);
                bf[2 * p][0] = r0; bf[2 * p][1] = r1;
                bf[2 * p + 1][0] = r2; bf[2 * p + 1][1] = r3;
            }
            #pragma unroll
            for (int mf = 0; mf < 4; mf++)
                #pragma unroll
                for (int nf = 0; nf < 4; nf++)
                    mma_f16(acc[mf][nf][0], acc[mf][nf][1], acc[mf][nf][2], acc[mf][nf][3],
                            af[mf][0], af[mf][1], af[mf][2], af[mf][3],
                            bf[nf][0], bf[nf][1]);
        }
        mbar_arrive(mb + stC * 16 + 8);

        if (kt + 3 < KT) {
            mbar_wait(mb + stC * 16 + 8, (pphBits >> stC) & 1u);
            pphBits ^= (1u << stC);
            issue(kt + 3, stC);
            cpasync_mbar_arrive_noinc(mb + stC * 16);
        }
        stC = (stC == 2) ? 0 : stC + 1;
    }

    const long long m0 = (long long)blockIdx.y * 128;
    const int n0 = blockIdx.x * 128;
    const float* bp = bias + (long long)bb * N + n0;

    if (awOut) {
        __syncthreads();
        uint32_t* sw = (uint32_t*)dsm;
        #pragma unroll
        for (int mf = 0; mf < 4; mf++) {
            int rl = (wm * 4 + mf) * 16 + g;
            #pragma unroll
            for (int nf = 0; nf < 4; nf++) {
                int col = (wn * 4 + nf) * 8 + 2 * t;
                float2 bv = *(const float2*)(bp + col);
                int dl = (wn * 4 + nf) * 4 + t;
                {
                    float hid = acc[mf][nf][0] + bv.x;
                    float gat = acc[mf][nf][1] + bv.y;
                    float z = __fdividef(1.f, 1.f + __expf(-gat));
                    float ht = (hid >= 0.f) ? (hid + 0.5f) : __fdividef(1.f, 1.f + __expf(-hid));
                    __half2 hv = __floats2half2_rn(1.0f - z, z * ht);
                    sw[rl * 65 + dl] = *(uint32_t*)&hv;
                }
                {
                    float hid = acc[mf][nf][2] + bv.x;
                    float gat = acc[mf][nf][3] + bv.y;
                    float z = __fdividef(1.f, 1.f + __expf(-gat));
                    float ht = (hid >= 0.f) ? (hid + 0.5f) : __fdividef(1.f, 1.f + __expf(-hid));
                    __half2 hv = __floats2half2_rn(1.0f - z, z * ht);
                    sw[(rl + 8) * 65 + dl] = *(uint32_t*)&hv;
                }
            }
        }
        __syncthreads();
        __half2* ap = awOut + (long long)bb * SEQ * DI;
        const int d0 = n0 >> 1;
        #pragma unroll
        for (int i = 0; i < 8; i++) {
            int lin = i * 256 + tid;
            int row = lin >> 4, c16 = lin & 15;
            uint4 u = make_uint4(sw[row * 65 + c16 * 4 + 0], sw[row * 65 + c16 * 4 + 1],
                                 sw[row * 65 + c16 * 4 + 2], sw[row * 65 + c16 * 4 + 3]);
            *(uint4*)(ap + (m0 + row) * DI + d0 + c16 * 4) = u;
        }
        // fused scan_a: 64-row chunk composites (2 per tile)
        {
            const int d = tid >> 2;
            const int q = tid & 3;
            float Acc = 1.f, Wcc = 0.f;
            #pragma unroll 8
            for (int i = 0; i < 32; i++) {
                uint32_t u = sw[(q * 32 + i) * 65 + d];
                __half2 hv = *(__half2*)&u;
                float a = __low2float(hv), w = __high2float(hv);
                Acc = a * Acc;
                Wcc = fmaf(a, Wcc, w);
            }
            const int base = lane & ~3;
            float A0 = __shfl_sync(0xffffffffu, Acc, base);
            float W0 = __shfl_sync(0xffffffffu, Wcc, base);
            float A1 = __shfl_sync(0xffffffffu, Acc, base + 1);
            float W1 = __shfl_sync(0xffffffffu, Wcc, base + 1);
            float A2 = __shfl_sync(0xffffffffu, Acc, base + 2);
            float W2 = __shfl_sync(0xffffffffu, Wcc, base + 2);
            float A3 = __shfl_sync(0xffffffffu, Acc, base + 3);
            float W3 = __shfl_sync(0xffffffffu, Wcc, base + 3);
            if (q == 0) {
                int o = (bb * NCH + 2 * blockIdx.y) * DI + d0 + d;
                cA[o] = A1 * A0;
                cW[o] = fmaf(A1, W0, W1);
                cA[o + DI] = A3 * A2;
                cW[o + DI] = fmaf(A3, W2, W3);
            }
        }
        return;
    }

    float* Cp = C + (long long)bb * sC;
    const float* Rp = resid ? (resid + (long long)bb * sC) : nullptr;
    #pragma unroll
    for (int mf = 0; mf < 4; mf++) {
        long long r0 = m0 + (wm * 4 + mf) * 16 + g;
        #pragma unroll
        for (int nf = 0; nf < 4; nf++) {
            int col = (wn * 4 + nf) * 8 + 2 * t;
            float2 bv = *(const float2*)(bp + col);
            long long o0 = r0 * N + n0 + col;
            long long o1 = (r0 + 8) * N + n0 + col;
            float2 v0 = make_float2(acc[mf][nf][0] + bv.x, acc[mf][nf][1] + bv.y);
            float2 v1 = make_float2(acc[mf][nf][2] + bv.x, acc[mf][nf][3] + bv.y);
            if (Rp) {
                float2 q0 = *(const float2*)(Rp + o0);
                float2 q1 = *(const float2*)(Rp + o1);
                v0.x += q0.x; v0.y += q0.y;
                v1.x += q1.x; v1.y += q1.y;
            }
            *(float2*)(Cp + o0) = v0;
            *(float2*)(Cp + o1) = v1;
        }
    }
}

// ---------------- 5/6. scan prefix + replay ----------------
__global__ void scan_b_kernel(const float* __restrict__ cA, const float* __restrict__ cW,
                              float* __restrict__ h0, float* __restrict__ auxp) {
    if (blockIdx.x == 0 && threadIdx.x == 0) *auxp = 0.0f;
    int b = blockIdx.x / 5, gA = blockIdx.x % 5;
    int d = gA * 256 + threadIdx.x;
    float h = 0.f;
    #pragma unroll
    for (int c = 0; c < NCH; c++) {
        int o = (b * NCH + c) * DI + d;
        h0[o] = h;
        h = fmaf(cA[o], h, cW[o]);
    }
}

// 32-row tiles, CH=64 -> 2 tiles per block; grid = NB*5*NCH = 1280
__global__ __launch_bounds__(256) void scan_c_kernel(const __half2* __restrict__ aw,
                                                     const float* __restrict__ h0,
                                                     __half* __restrict__ hsb,
                                                     float* __restrict__ ns) {
    __shared__ uint32_t sa[32][256];
    __shared__ __half sO[32][256];
    int bid = blockIdx.x;
    int b = bid / (5 * NCH);
    int rem = bid % (5 * NCH);
    int gA = rem / NCH, c = rem % NCH;
    int d0 = gA * 256;
    const int tid = threadIdx.x;
    const uint32_t* ab = (const uint32_t*)(aw + (long long)b * SEQ * DI);
    __half* hb = hsb + (long long)b * SEQ * DI;
    float h = h0[(b * NCH + c) * DI + d0 + tid];
    for (int s0 = c * CH; s0 < (c + 1) * CH; s0 += 32) {
        #pragma unroll
        for (int i = 0; i < 8; i++) {
            int lin = i * 256 + tid;
            int row = lin >> 6;
            int c4 = (lin & 63) * 4;
            *(uint4*)&sa[row][c4] = *(const uint4*)(ab + (long long)(s0 + row) * DI + d0 + c4);
        }
        __syncthreads();
        #pragma unroll
        for (int s = 0; s < 32; s++) {
            uint32_t u = sa[s][tid];
            __half2 hv = *(__half2*)&u;
            h = fmaf(__low2float(hv), h, __high2float(hv));
            sO[s][tid] = __float2half(h);
        }
        __syncthreads();
        #pragma unroll
        for (int i = 0; i < 4; i++) {
            int lin = i * 256 + tid;
            int row = lin >> 5;
            int cc = (lin & 31) * 8;
            *(uint4*)(hb + (long long)(s0 + row) * DI + d0 + cc) = *(uint4*)&sO[row][cc];
        }
        __syncthreads();
    }
    if (c == NCH - 1) ns[b * DI + d0 + tid] = h;
}

// ---------------- launch ----------------
extern "C" void kernel_launch(void* const* d_in, const int* in_sizes, int n_in,
                              void* d_out, int out_size) {
    const float* inputs   = (const float*)d_in[0];
    const float* norm_w   = (const float*)d_in[1];
    const float* router_w = (const float*)d_in[2];
    const float* router_b = (const float*)d_in[3];
    const float* w_in     = (const float*)d_in[4];
    const float* b_in     = (const float*)d_in[5];
    const float* w_out    = (const float*)d_in[6];
    const float* b_out    = (const float*)d_in[7];
    float* out = (float*)d_out;

    __half *xnh, *WiT, *WoT, *hs;
    __half2* aw;
    float *partial, *probs, *bi, *bo, *cA, *cW, *h0;
    cudaGetSymbolAddress((void**)&xnh, g_xnh);
    cudaGetSymbolAddress((void**)&partial, g_partial);
    cudaGetSymbolAddress((void**)&probs, g_probs);
    cudaGetSymbolAddress((void**)&WiT, g_WiT);
    cudaGetSymbolAddress((void**)&bi, g_bi);
    cudaGetSymbolAddress((void**)&WoT, g_WoT);
    cudaGetSymbolAddress((void**)&bo, g_bo);
    cudaGetSymbolAddress((void**)&aw, g_aw);
    cudaGetSymbolAddress((void**)&hs, g_hs);
    cudaGetSymbolAddress((void**)&cA, g_cA);
    cudaGetSymbolAddress((void**)&cW, g_cW);
    cudaGetSymbolAddress((void**)&h0, g_h0);

    const int DYN = 3 * STAGE_BYTES + 64;
    cudaFuncSetAttribute(hgemm_kernel, cudaFuncAttributeMaxDynamicSharedMemorySize, DYN);

    norm_pool_kernel<<<NB * 128, 256>>>(inputs, norm_w, xnh, partial);
    router_kernel<<<NB, 1024>>>(partial, router_w, router_b, probs);
    mix_all_kernel<<<3896, 256>>>(WiT, WoT, bi, bo, w_in, w_out, b_in, b_out, probs);
    {   // GEMM1 -> aw pairs + fused 64-row chunk composites (4th launch: profiled)
        dim3 grid(D2 / 128, SEQ / 128, NB);
        hgemm_kernel<<<grid, 256, DYN>>>(xnh, WiT, bi, nullptr, nullptr, aw, cA, cW, HID, D2,
                                         (long long)SEQ * HID, (long long)HID * D2, 0);
    }
    scan_b_kernel<<<NB * 5, 256>>>(cA, cW, h0, out + (long long)out_size - 1);
    scan_c_kernel<<<NB * 5 * NCH, 256>>>(aw, h0, hs, out + (long long)NB * SEQ * HID);
    {   // GEMM2: out = hs @ WoT^T + bo + inputs
        dim3 grid(HID / 128, SEQ / 128, NB);
        hgemm_kernel<<<grid, 256, DYN>>>(hs, WoT, bo, inputs, out, nullptr, nullptr, nullptr,
                                         DI, HID,
                                         (long long)SEQ * DI, (long long)DI * HID,
                                         (long long)SEQ * HID);
    }
}

// round 16
// speedup vs baseline: 1.0225x; 1.0225x over previous
#include <cuda_runtime.h>
#include <cuda_fp16.h>
#include <math.h>
#include <stdint.h>

#define HID 1024
#define NE 3
#define DI 1280
#define D2 2560
#define NB 4
#define SEQ 4096
#define EPSV 1e-6f
#define NCH 32
#define CH  128

// ---------------- scratch (device globals) ----------------
__device__ __half g_xnh[(size_t)NB * SEQ * HID];
__device__ float g_partial[NB * 128 * HID];
__device__ float g_probs[NB * NE];
__device__ __half g_WiT[(size_t)NB * HID * D2];   // hid/gate interleaved rows
__device__ float g_bi[NB * D2];
__device__ __half g_WoT[(size_t)NB * DI * HID];
__device__ float g_bo[NB * HID];
__device__ __half2 g_aw[(size_t)NB * SEQ * DI];
__device__ __half g_hs[(size_t)NB * SEQ * DI];
__device__ float g_cA[NB * NCH * DI];
__device__ float g_cW[NB * NCH * DI];

// ---------------- PTX helpers ----------------
__device__ __forceinline__ uint32_t smem_u32(const void* p) {
    uint32_t a;
    asm("{ .reg .u64 t; cvta.to.shared.u64 t, %1; cvt.u32.u64 %0, t; }" : "=r"(a) : "l"(p));
    return a;
}
__device__ __forceinline__ void cpa16(uint32_t dst, const void* src) {
    asm volatile("{\n .reg .u64 g;\n cvta.to.global.u64 g, %1;\n"
                 " cp.async.cg.shared.global [%0], [g], 16;\n}"
                 :: "r"(dst), "l"(src));
}
__device__ __forceinline__ void ldsm_x4(uint32_t& r0, uint32_t& r1, uint32_t& r2, uint32_t& r3,
                                        uint32_t addr) {
    asm volatile("ldmatrix.sync.aligned.m8n8.x4.shared.b16 {%0,%1,%2,%3}, [%4];"
                 : "=r"(r0), "=r"(r1), "=r"(r2), "=r"(r3) : "r"(addr));
}
__device__ __forceinline__ void mma_f16(float& d0, float& d1, float& d2, float& d3,
                                        uint32_t a0, uint32_t a1, uint32_t a2, uint32_t a3,
                                        uint32_t b0, uint32_t b1) {
    asm volatile("mma.sync.aligned.m16n8k16.row.col.f32.f16.f16.f32 "
                 "{%0,%1,%2,%3}, {%4,%5,%6,%7}, {%8,%9}, {%0,%1,%2,%3};"
                 : "+f"(d0), "+f"(d1), "+f"(d2), "+f"(d3)
                 : "r"(a0), "r"(a1), "r"(a2), "r"(a3), "r"(b0), "r"(b1));
}
__device__ __forceinline__ void mbar_init(uint32_t a, uint32_t cnt) {
    asm volatile("mbarrier.init.shared.b64 [%0], %1;" :: "r"(a), "r"(cnt) : "memory");
}
__device__ __forceinline__ void mbar_arrive(uint32_t a) {
    asm volatile("mbarrier.arrive.shared.b64 _, [%0];" :: "r"(a) : "memory");
}
__device__ __forceinline__ void cpasync_mbar_arrive_noinc(uint32_t a) {
    asm volatile("cp.async.mbarrier.arrive.noinc.shared.b64 [%0];" :: "r"(a) : "memory");
}
__device__ __forceinline__ void mbar_wait(uint32_t a, uint32_t parity) {
    asm volatile("{\n\t.reg .pred P;\n"
                 "LW%=:\n\tmbarrier.try_wait.parity.acquire.cta.shared::cta.b64 P, [%0], %1, 0x989680;\n"
                 "\t@!P bra LW%=;\n\t}"
                 :: "r"(a), "r"(parity) : "memory");
}

// ---------------- 1. fused RMSNorm -> fp16 + pooled partial ----------------
__global__ __launch_bounds__(256) void norm_pool_kernel(const float* __restrict__ in,
                                                        const float* __restrict__ nw,
                                                        __half* __restrict__ xnh,
                                                        float* __restrict__ partial) {
    __shared__ float sp[8][1024];
    const int blk = blockIdx.x;
    const int b = blk >> 7, ch = blk & 127;
    const int wid = threadIdx.x >> 5, lane = threadIdx.x & 31;

    float4 wv[8];
    #pragma unroll
    for (int i = 0; i < 8; i++) wv[i] = *(const float4*)(nw + i * 128 + lane * 4);

    float4 pacc[8];
    #pragma unroll
    for (int i = 0; i < 8; i++) pacc[i] = make_float4(0.f, 0.f, 0.f, 0.f);

    const long long rowBase = (long long)b * SEQ + ch * 32 + wid * 4;
    #pragma unroll
    for (int r = 0; r < 4; r++) {
        const float* rp = in + (rowBase + r) * HID;
        float4 v[8];
        float ss = 0.f;
        #pragma unroll
        for (int i = 0; i < 8; i++) {
            v[i] = *(const float4*)(rp + i * 128 + lane * 4);
            ss += v[i].x * v[i].x + v[i].y * v[i].y + v[i].z * v[i].z + v[i].w * v[i].w;
        }
        #pragma unroll
        for (int o = 16; o > 0; o >>= 1) ss += __shfl_xor_sync(0xffffffffu, ss, o);
        float scale = rsqrtf(ss * (1.0f / HID) + EPSV);
        __half* op = xnh + (rowBase + r) * HID;
        #pragma unroll
        for (int i = 0; i < 8; i++) {
            float x0 = v[i].x * scale * wv[i].x;
            float x1 = v[i].y * scale * wv[i].y;
            float x2 = v[i].z * scale * wv[i].z;
            float x3 = v[i].w * scale * wv[i].w;
            pacc[i].x += x0; pacc[i].y += x1; pacc[i].z += x2; pacc[i].w += x3;
            __half2 p0 = __floats2half2_rn(x0, x1);
            __half2 p1 = __floats2half2_rn(x2, x3);
            uint2 u;
            u.x = *(uint32_t*)&p0;
            u.y = *(uint32_t*)&p1;
            *(uint2*)(op + i * 128 + lane * 4) = u;
        }
    }
    #pragma unroll
    for (int i = 0; i < 8; i++) *(float4*)(&sp[wid][i * 128 + lane * 4]) = pacc[i];
    __syncthreads();
    float* pp = partial + (long long)(b * 128 + ch) * HID;
    int h = threadIdx.x * 4;
    float4 s = make_float4(0.f, 0.f, 0.f, 0.f);
    #pragma unroll
    for (int w = 0; w < 8; w++) {
        float4 q = *(float4*)(&sp[w][h]);
        s.x += q.x; s.y += q.y; s.z += q.z; s.w += q.w;
    }
    *(float4*)(pp + h) = s;
}

// ---------------- 2. router (one block per batch) ----------------
__global__ void router_kernel(const float* __restrict__ partial,
                              const float* __restrict__ rw,
                              const float* __restrict__ rb,
                              float* __restrict__ probs) {
    __shared__ float red[3][32];
    const int b = blockIdx.x;
    const int h = threadIdx.x;
    const int wid = h >> 5, lid = h & 31;
    float s = 0.f;
    #pragma unroll 16
    for (int c = 0; c < 128; c++) s += partial[(long long)(b * 128 + c) * HID + h];
    float p = s * (1.0f / SEQ);
    float a0 = p * rw[h * NE + 0];
    float a1 = p * rw[h * NE + 1];
    float a2 = p * rw[h * NE + 2];
    #pragma unroll
    for (int o = 16; o > 0; o >>= 1) {
        a0 += __shfl_xor_sync(0xffffffffu, a0, o);
        a1 += __shfl_xor_sync(0xffffffffu, a1, o);
        a2 += __shfl_xor_sync(0xffffffffu, a2, o);
    }
    if (lid == 0) { red[0][wid] = a0; red[1][wid] = a1; red[2][wid] = a2; }
    __syncthreads();
    if (h == 0) {
        float l0 = rb[0], l1 = rb[1], l2 = rb[2];
        #pragma unroll
        for (int w = 0; w < 32; w++) { l0 += red[0][w]; l1 += red[1][w]; l2 += red[2][w]; }
        float mx = fmaxf(l0, fmaxf(l1, l2));
        float e0 = expf(l0 - mx), e1 = expf(l1 - mx), e2 = expf(l2 - mx);
        float inv = 1.0f / (e0 + e1 + e2);
        probs[b * 3 + 0] = e0 * inv;
        probs[b * 3 + 1] = e1 * inv;
        probs[b * 3 + 2] = e2 * inv;
    }
}

// ---------------- 3. fused mixing (half2 stores) ----------------
__device__ __forceinline__ void mixT_body(__half* __restrict__ dst,
                                          const float* __restrict__ src,
                                          const float* __restrict__ probs,
                                          int K, int N, int bx, int by, int tid, int perm) {
    __shared__ float t0[32][33], t1[32][33], t2[32][33];
    int tx = tid & 31, ty = tid >> 5;
    int k0 = by * 32, n0 = bx * 32;
    long long eSz = (long long)K * N;
    #pragma unroll
    for (int i = 0; i < 4; i++) {
        int k = k0 + ty + i * 8;
        long long o = (long long)k * N + n0 + tx;
        t0[ty + i * 8][tx] = src[o];
        t1[ty + i * 8][tx] = src[eSz + o];
        t2[ty + i * 8][tx] = src[2 * eSz + o];
    }
    __syncthreads();
    int kp = tid & 15;
    int nOff = tid >> 4;
    #pragma unroll
    for (int b = 0; b < NB; b++) {
        float p0 = probs[b * 3 + 0], p1 = probs[b * 3 + 1], p2 = probs[b * 3 + 2];
        #pragma unroll
        for (int i = 0; i < 2; i++) {
            int n = n0 + nOff + i * 16;
            int nl = nOff + i * 16;
            float va = p0 * t0[2 * kp][nl] + p1 * t1[2 * kp][nl] + p2 * t2[2 * kp][nl];
            float vb = p0 * t0[2 * kp + 1][nl] + p1 * t1[2 * kp + 1][nl] + p2 * t2[2 * kp + 1][nl];
            long long r = perm ? ((n < DI) ? 2 * n : 2 * (n - DI) + 1) : n;
            __half2 hv = __floats2half2_rn(va, vb);
            *(uint32_t*)(dst + (long long)b * eSz + r * K + k0 + 2 * kp) = *(uint32_t*)&hv;
        }
    }
}

__global__ void mix_all_kernel(__half* __restrict__ WiT, __half* __restrict__ WoT,
                               float* __restrict__ bi, float* __restrict__ bo,
                               const float* __restrict__ w_in, const float* __restrict__ w_out,
                               const float* __restrict__ b_in, const float* __restrict__ b_out,
                               const float* __restrict__ probs) {
    int bid = blockIdx.x, tid = threadIdx.x;
    if (bid < 2560) {
        mixT_body(WiT, w_in, probs, HID, D2, bid % 80, bid / 80, tid, 1);
    } else if (bid < 3840) {
        int id = bid - 2560;
        mixT_body(WoT, w_out, probs, DI, HID, id % 32, id / 32, tid, 0);
    } else if (bid < 3880) {
        int i = (bid - 3840) * 256 + tid;
        if (i < NB * D2) {
            int b = i / D2, j = i - b * D2;
            float v = probs[b * 3 + 0] * b_in[j] + probs[b * 3 + 1] * b_in[D2 + j] +
                      probs[b * 3 + 2] * b_in[2 * D2 + j];
            long long r = (j < DI) ? 2 * j : 2 * (j - DI) + 1;
            bi[(long long)b * D2 + r] = v;
        }
    } else {
        int i = (bid - 3880) * 256 + tid;
        if (i < NB * HID) {
            int b = i / HID, j = i - b * HID;
            bo[i] = probs[b * 3 + 0] * b_out[j] + probs[b * 3 + 1] * b_out[HID + j] +
                    probs[b * 3 + 2] * b_out[2 * HID + j];
        }
    }
}

// ---------------- 4/6. fp16 GEMM: mbarrier-decoupled cp.async 3-stage BK=64 ----------------
#define STAGE_BYTES 32768
#define MBAR_OFF (3 * STAGE_BYTES)

__global__ __launch_bounds__(256, 2) void hgemm_kernel(
    const __half* __restrict__ A, const __half* __restrict__ B,
    const float* __restrict__ bias, const float* __restrict__ resid,
    float* __restrict__ C, __half2* __restrict__ awOut,
    float* __restrict__ cA, float* __restrict__ cW, int K, int N,
    long long sA, long long sB, long long sC) {
    extern __shared__ uint8_t dsm[];
    const uint32_t smb = smem_u32(dsm);
    const uint32_t mb = smb + MBAR_OFF;
    const int tid = threadIdx.x;
    const int wid = tid >> 5;
    const int lane = tid & 31;
    const int bb = blockIdx.z;

    const __half* Abase = A + (long long)bb * sA + (long long)blockIdx.y * 128 * K;
    const __half* Bbase = B + (long long)bb * sB + (long long)blockIdx.x * 128 * K;

    const int g = lane >> 2, t = lane & 3;
    const int wm = wid >> 2;
    const int wn = wid & 3;

    float acc[4][4][4];
    #pragma unroll
    for (int i = 0; i < 4; i++)
        #pragma unroll
        for (int j = 0; j < 4; j++)
            #pragma unroll
            for (int q = 0; q < 4; q++) acc[i][j][q] = 0.f;

    const int KT = K >> 6;

    if (tid == 0) {
        #pragma unroll
        for (int s = 0; s < 3; s++) {
            mbar_init(mb + s * 16, 256);
            mbar_init(mb + s * 16 + 8, 256);
        }
    }
    __syncthreads();

    auto issue = [&](int kt, int stg) {
        uint32_t sb = smb + stg * STAGE_BYTES;
        #pragma unroll
        for (int u = 0; u < 4; u++) {
            int c = tid + u * 256;
            int row = c >> 3, k16 = c & 7;
            int phys = k16 ^ (row & 7);
            uint32_t off = row * 128 + phys * 16;
            cpa16(sb + off, Abase + (long long)row * K + kt * 64 + k16 * 8);
            cpa16(sb + 16384 + off, Bbase + (long long)row * K + kt * 64 + k16 * 8);
        }
    };

    #pragma unroll
    for (int k = 0; k < 3; k++) {
        issue(k, k);
        cpasync_mbar_arrive_noinc(mb + k * 16);
    }

    const int mi = lane >> 3;
    const int l7 = lane & 7;

    uint32_t cphBits = 0, pphBits = 0;
    int stC = 0;
    for (int kt = 0; kt < KT; kt++) {
        mbar_wait(mb + stC * 16, (cphBits >> stC) & 1u);
        cphBits ^= (1u << stC);

        uint32_t sa = smb + stC * STAGE_BYTES;
        uint32_t sbm = sa + 16384;
        #pragma unroll
        for (int ks = 0; ks < 4; ks++) {
            uint32_t af[4][4], bf[4][2];
            #pragma unroll
            for (int mf = 0; mf < 4; mf++) {
                int row = wm * 64 + mf * 16 + l7 + (mi & 1) * 8;
                int chunk = 2 * ks + (mi >> 1);
                int phys = chunk ^ (row & 7);
                ldsm_x4(af[mf][0], af[mf][1], af[mf][2], af[mf][3],
                        sa + row * 128 + phys * 16);
            }
            #pragma unroll
            for (int p = 0; p < 2; p++) {
                int row = wn * 32 + p * 16 + l7 + (mi >> 1) * 8;
                int chunk = 2 * ks + (mi & 1);
                int phys = chunk ^ (row & 7);
                uint32_t r0, r1, r2, r3;
                ldsm_x4(r0, r1, r2, r3, sbm + row * 128 + phys * 16);
                bf[2 * p][0] = r0; bf[2 * p][1] = r1;
                bf[2 * p + 1][0] = r2; bf[2 * p + 1][1] = r3;
            }
            #pragma unroll
            for (int mf = 0; mf < 4; mf++)
                #pragma unroll
                for (int nf = 0; nf < 4; nf++)
                    mma_f16(acc[mf][nf][0], acc[mf][nf][1], acc[mf][nf][2], acc[mf][nf][3],
                            af[mf][0], af[mf][1], af[mf][2], af[mf][3],
                            bf[nf][0], bf[nf][1]);
        }
        mbar_arrive(mb + stC * 16 + 8);

        if (kt + 3 < KT) {
            mbar_wait(mb + stC * 16 + 8, (pphBits >> stC) & 1u);
            pphBits ^= (1u << stC);
            issue(kt + 3, stC);
            cpasync_mbar_arrive_noinc(mb + stC * 16);
        }
        stC = (stC == 2) ? 0 : stC + 1;
    }

    const long long m0 = (long long)blockIdx.y * 128;
    const int n0 = blockIdx.x * 128;
    const float* bp = bias + (long long)bb * N + n0;

    if (awOut) {
        __syncthreads();
        uint32_t* sw = (uint32_t*)dsm;
        #pragma unroll
        for (int mf = 0; mf < 4; mf++) {
            int rl = (wm * 4 + mf) * 16 + g;
            #pragma unroll
            for (int nf = 0; nf < 4; nf++) {
                int col = (wn * 4 + nf) * 8 + 2 * t;
                float2 bv = *(const float2*)(bp + col);
                int dl = (wn * 4 + nf) * 4 + t;
                {
                    float hid = acc[mf][nf][0] + bv.x;
                    float gat = acc[mf][nf][1] + bv.y;
                    float z = __fdividef(1.f, 1.f + __expf(-gat));
                    float ht = (hid >= 0.f) ? (hid + 0.5f) : __fdividef(1.f, 1.f + __expf(-hid));
                    __half2 hv = __floats2half2_rn(1.0f - z, z * ht);
                    sw[rl * 65 + dl] = *(uint32_t*)&hv;
                }
                {
                    float hid = acc[mf][nf][2] + bv.x;
                    float gat = acc[mf][nf][3] + bv.y;
                    float z = __fdividef(1.f, 1.f + __expf(-gat));
                    float ht = (hid >= 0.f) ? (hid + 0.5f) : __fdividef(1.f, 1.f + __expf(-hid));
                    __half2 hv = __floats2half2_rn(1.0f - z, z * ht);
                    sw[(rl + 8) * 65 + dl] = *(uint32_t*)&hv;
                }
            }
        }
        __syncthreads();
        __half2* ap = awOut + (long long)bb * SEQ * DI;
        const int d0 = n0 >> 1;
        #pragma unroll
        for (int i = 0; i < 8; i++) {
            int lin = i * 256 + tid;
            int row = lin >> 4, c16 = lin & 15;
            uint4 u = make_uint4(sw[row * 65 + c16 * 4 + 0], sw[row * 65 + c16 * 4 + 1],
                                 sw[row * 65 + c16 * 4 + 2], sw[row * 65 + c16 * 4 + 3]);
            *(uint4*)(ap + (m0 + row) * DI + d0 + c16 * 4) = u;
        }
        // fused scan_a: chunk composite over the 128 rows of this tile
        {
            const int d = tid >> 2;
            const int q = tid & 3;
            float Acc = 1.f, Wcc = 0.f;
            #pragma unroll 8
            for (int i = 0; i < 32; i++) {
                uint32_t u = sw[(q * 32 + i) * 65 + d];
                __half2 hv = *(__half2*)&u;
                float a = __low2float(hv), w = __high2float(hv);
                Acc = a * Acc;
                Wcc = fmaf(a, Wcc, w);
            }
            const int base = lane & ~3;
            float Af = __shfl_sync(0xffffffffu, Acc, base);
            float Wf = __shfl_sync(0xffffffffu, Wcc, base);
            #pragma unroll
            for (int j = 1; j < 4; j++) {
                float Aj = __shfl_sync(0xffffffffu, Acc, base + j);
                float Wj = __shfl_sync(0xffffffffu, Wcc, base + j);
                Wf = fmaf(Aj, Wf, Wj);
                Af = Aj * Af;
            }
            if (q == 0) {
                int o = (bb * NCH + blockIdx.y) * DI + d0 + d;
                cA[o] = Af;
                cW[o] = Wf;
            }
        }
        return;
    }

    float* Cp = C + (long long)bb * sC;
    const float* Rp = resid ? (resid + (long long)bb * sC) : nullptr;
    #pragma unroll
    for (int mf = 0; mf < 4; mf++) {
        long long r0 = m0 + (wm * 4 + mf) * 16 + g;
        #pragma unroll
        for (int nf = 0; nf < 4; nf++) {
            int col = (wn * 4 + nf) * 8 + 2 * t;
            float2 bv = *(const float2*)(bp + col);
            long long o0 = r0 * N + n0 + col;
            long long o1 = (r0 + 8) * N + n0 + col;
            float2 v0 = make_float2(acc[mf][nf][0] + bv.x, acc[mf][nf][1] + bv.y);
            float2 v1 = make_float2(acc[mf][nf][2] + bv.x, acc[mf][nf][3] + bv.y);
            if (Rp) {
                float2 q0 = *(const float2*)(Rp + o0);
                float2 q1 = *(const float2*)(Rp + o1);
                v0.x += q0.x; v0.y += q0.y;
                v1.x += q1.x; v1.y += q1.y;
            }
            *(float2*)(Cp + o0) = v0;
            *(float2*)(Cp + o1) = v1;
        }
    }
}

// ---------------- 5. scan replay with inline chunk-prefix (scan_b fused) ----------------
__global__ __launch_bounds__(256) void scan_c_kernel(const __half2* __restrict__ aw,
                                                     const float* __restrict__ cA,
                                                     const float* __restrict__ cW,
                                                     __half* __restrict__ hsb,
                                                     float* __restrict__ ns,
                                                     float* __restrict__ auxp) {
    __shared__ uint32_t sa[16][256];
    __shared__ __half sO[16][256];
    int bid = blockIdx.x;
    if (bid == 0 && threadIdx.x == 0) *auxp = 0.0f;
    int b = bid / (5 * NCH);
    int rem = bid % (5 * NCH);
    int gA = rem / NCH, c = rem % NCH;
    int d0 = gA * 256;
    const int tid = threadIdx.x;

    // inline prefix over chunk composites 0..c-1 (cA/cW are L2-hot from GEMM1)
    float h = 0.f;
    {
        const float* pA = cA + (long long)b * NCH * DI + d0 + tid;
        const float* pW = cW + (long long)b * NCH * DI + d0 + tid;
        int j = 0;
        for (; j + 8 <= c; j += 8) {
            float a[8], w[8];
            #pragma unroll
            for (int u = 0; u < 8; u++) {
                a[u] = pA[(long long)(j + u) * DI];
                w[u] = pW[(long long)(j + u) * DI];
            }
            #pragma unroll
            for (int u = 0; u < 8; u++) h = fmaf(a[u], h, w[u]);
        }
        for (; j < c; j++)
            h = fmaf(pA[(long long)j * DI], h, pW[(long long)j * DI]);
    }

    const uint32_t* ab = (const uint32_t*)(aw + (long long)b * SEQ * DI);
    __half* hb = hsb + (long long)b * SEQ * DI;
    for (int s0 = c * CH; s0 < (c + 1) * CH; s0 += 16) {
        #pragma unroll
        for (int i = 0; i < 4; i++) {
            int lin = i * 256 + tid;
            int row = lin >> 6;
            int c4 = (lin & 63) * 4;
            *(uint4*)&sa[row][c4] = *(const uint4*)(ab + (long long)(s0 + row) * DI + d0 + c4);
        }
        __syncthreads();
        #pragma unroll
        for (int s = 0; s < 16; s++) {
            uint32_t u = sa[s][tid];
            __half2 hv = *(__half2*)&u;
            h = fmaf(__low2float(hv), h, __high2float(hv));
            sO[s][tid] = __float2half(h);
        }
        __syncthreads();
        #pragma unroll
        for (int i = 0; i < 2; i++) {
            int lin = i * 256 + tid;
            int row = lin >> 5;
            int cc = (lin & 31) * 8;
            *(uint4*)(hb + (long long)(s0 + row) * DI + d0 + cc) = *(uint4*)&sO[row][cc];
        }
        __syncthreads();
    }
    if (c == NCH - 1) ns[b * DI + d0 + tid] = h;
}

// ---------------- launch ----------------
extern "C" void kernel_launch(void* const* d_in, const int* in_sizes, int n_in,
                              void* d_out, int out_size) {
    const float* inputs   = (const float*)d_in[0];
    const float* norm_w   = (const float*)d_in[1];
    const float* router_w = (const float*)d_in[2];
    const float* router_b = (const float*)d_in[3];
    const float* w_in     = (const float*)d_in[4];
    const float* b_in     = (const float*)d_in[5];
    const float* w_out    = (const float*)d_in[6];
    const float* b_out    = (const float*)d_in[7];
    float* out = (float*)d_out;

    __half *xnh, *WiT, *WoT, *hs;
    __half2* aw;
    float *partial, *probs, *bi, *bo, *cA, *cW;
    cudaGetSymbolAddress((void**)&xnh, g_xnh);
    cudaGetSymbolAddress((void**)&partial, g_partial);
    cudaGetSymbolAddress((void**)&probs, g_probs);
    cudaGetSymbolAddress((void**)&WiT, g_WiT);
    cudaGetSymbolAddress((void**)&bi, g_bi);
    cudaGetSymbolAddress((void**)&WoT, g_WoT);
    cudaGetSymbolAddress((void**)&bo, g_bo);
    cudaGetSymbolAddress((void**)&aw, g_aw);
    cudaGetSymbolAddress((void**)&hs, g_hs);
    cudaGetSymbolAddress((void**)&cA, g_cA);
    cudaGetSymbolAddress((void**)&cW, g_cW);

    const int DYN = 3 * STAGE_BYTES + 64;
    cudaFuncSetAttribute(hgemm_kernel, cudaFuncAttributeMaxDynamicSharedMemorySize, DYN);

    norm_pool_kernel<<<NB * 128, 256>>>(inputs, norm_w, xnh, partial);
    router_kernel<<<NB, 1024>>>(partial, router_w, router_b, probs);
    mix_all_kernel<<<3896, 256>>>(WiT, WoT, bi, bo, w_in, w_out, b_in, b_out, probs);
    {   // GEMM1 -> aw pairs + fused chunk composites (4th launch: profiled)
        dim3 grid(D2 / 128, SEQ / 128, NB);
        hgemm_kernel<<<grid, 256, DYN>>>(xnh, WiT, bi, nullptr, nullptr, aw, cA, cW, HID, D2,
                                         (long long)SEQ * HID, (long long)HID * D2, 0);
    }
    scan_c_kernel<<<NB * 5 * NCH, 256>>>(aw, cA, cW, hs,
                                         out + (long long)NB * SEQ * HID,
                                         out + (long long)out_size - 1);
    {   // GEMM2: out = hs @ WoT^T + bo + inputs
        dim3 grid(HID / 128, SEQ / 128, NB);
        hgemm_kernel<<<grid, 256, DYN>>>(hs, WoT, bo, inputs, out, nullptr, nullptr, nullptr,
                                         DI, HID,
                                         (long long)SEQ * DI, (long long)DI * HID,
                                         (long long)SEQ * HID);
    }
}

// round 17
// speedup vs baseline: 1.0394x; 1.0166x over previous
#include <cuda_runtime.h>
#include <cuda_fp16.h>
#include <math.h>
#include <stdint.h>

#define HID 1024
#define NE 3
#define DI 1280
#define D2 2560
#define NB 4
#define SEQ 4096
#define EPSV 1e-6f
#define NCH 32
#define CH  128

// ---------------- scratch (device globals) ----------------
__device__ __half g_xnh[(size_t)NB * SEQ * HID];
__device__ float g_partial[NB * 128 * HID];
__device__ float g_probs[NB * NE];
__device__ __half g_WiT[(size_t)NB * HID * D2];   // hid/gate interleaved rows
__device__ float g_bi[NB * D2];
__device__ __half g_WoT[(size_t)NB * DI * HID];
__device__ float g_bo[NB * HID];
__device__ __half2 g_aw[(size_t)NB * SEQ * DI];
__device__ __half g_hs[(size_t)NB * SEQ * DI];
__device__ float g_cA[NB * NCH * DI];
__device__ float g_cW[NB * NCH * DI];

// ---------------- PTX helpers ----------------
__device__ __forceinline__ uint32_t smem_u32(const void* p) {
    uint32_t a;
    asm("{ .reg .u64 t; cvta.to.shared.u64 t, %1; cvt.u32.u64 %0, t; }" : "=r"(a) : "l"(p));
    return a;
}
__device__ __forceinline__ void cpa16(uint32_t dst, const void* src) {
    asm volatile("{\n .reg .u64 g;\n cvta.to.global.u64 g, %1;\n"
                 " cp.async.cg.shared.global [%0], [g], 16;\n}"
                 :: "r"(dst), "l"(src));
}
__device__ __forceinline__ void ldsm_x4(uint32_t& r0, uint32_t& r1, uint32_t& r2, uint32_t& r3,
                                        uint32_t addr) {
    asm volatile("ldmatrix.sync.aligned.m8n8.x4.shared.b16 {%0,%1,%2,%3}, [%4];"
                 : "=r"(r0), "=r"(r1), "=r"(r2), "=r"(r3) : "r"(addr));
}
__device__ __forceinline__ void mma_f16(float& d0, float& d1, float& d2, float& d3,
                                        uint32_t a0, uint32_t a1, uint32_t a2, uint32_t a3,
                                        uint32_t b0, uint32_t b1) {
    asm volatile("mma.sync.aligned.m16n8k16.row.col.f32.f16.f16.f32 "
                 "{%0,%1,%2,%3}, {%4,%5,%6,%7}, {%8,%9}, {%0,%1,%2,%3};"
                 : "+f"(d0), "+f"(d1), "+f"(d2), "+f"(d3)
                 : "r"(a0), "r"(a1), "r"(a2), "r"(a3), "r"(b0), "r"(b1));
}
__device__ __forceinline__ void mbar_init(uint32_t a, uint32_t cnt) {
    asm volatile("mbarrier.init.shared.b64 [%0], %1;" :: "r"(a), "r"(cnt) : "memory");
}
__device__ __forceinline__ void mbar_arrive(uint32_t a) {
    asm volatile("mbarrier.arrive.shared.b64 _, [%0];" :: "r"(a) : "memory");
}
__device__ __forceinline__ void cpasync_mbar_arrive_noinc(uint32_t a) {
    asm volatile("cp.async.mbarrier.arrive.noinc.shared.b64 [%0];" :: "r"(a) : "memory");
}
__device__ __forceinline__ void mbar_wait(uint32_t a, uint32_t parity) {
    asm volatile("{\n\t.reg .pred P;\n"
                 "LW%=:\n\tmbarrier.try_wait.parity.acquire.cta.shared::cta.b64 P, [%0], %1, 0x989680;\n"
                 "\t@!P bra LW%=;\n\t}"
                 :: "r"(a), "r"(parity) : "memory");
}

// ---------------- 1. fused RMSNorm -> fp16 + pooled partial ----------------
__global__ __launch_bounds__(256) void norm_pool_kernel(const float* __restrict__ in,
                                                        const float* __restrict__ nw,
                                                        __half* __restrict__ xnh,
                                                        float* __restrict__ partial) {
    __shared__ float sp[8][1024];
    const int blk = blockIdx.x;
    const int b = blk >> 7, ch = blk & 127;
    const int wid = threadIdx.x >> 5, lane = threadIdx.x & 31;

    float4 wv[8];
    #pragma unroll
    for (int i = 0; i < 8; i++) wv[i] = *(const float4*)(nw + i * 128 + lane * 4);

    float4 pacc[8];
    #pragma unroll
    for (int i = 0; i < 8; i++) pacc[i] = make_float4(0.f, 0.f, 0.f, 0.f);

    const long long rowBase = (long long)b * SEQ + ch * 32 + wid * 4;
    #pragma unroll
    for (int r = 0; r < 4; r++) {
        const float* rp = in + (rowBase + r) * HID;
        float4 v[8];
        float ss = 0.f;
        #pragma unroll
        for (int i = 0; i < 8; i++) {
            v[i] = *(const float4*)(rp + i * 128 + lane * 4);
            ss += v[i].x * v[i].x + v[i].y * v[i].y + v[i].z * v[i].z + v[i].w * v[i].w;
        }
        #pragma unroll
        for (int o = 16; o > 0; o >>= 1) ss += __shfl_xor_sync(0xffffffffu, ss, o);
        float scale = rsqrtf(ss * (1.0f / HID) + EPSV);
        __half* op = xnh + (rowBase + r) * HID;
        #pragma unroll
        for (int i = 0; i < 8; i++) {
            float x0 = v[i].x * scale * wv[i].x;
            float x1 = v[i].y * scale * wv[i].y;
            float x2 = v[i].z * scale * wv[i].z;
            float x3 = v[i].w * scale * wv[i].w;
            pacc[i].x += x0; pacc[i].y += x1; pacc[i].z += x2; pacc[i].w += x3;
            __half2 p0 = __floats2half2_rn(x0, x1);
            __half2 p1 = __floats2half2_rn(x2, x3);
            uint2 u;
            u.x = *(uint32_t*)&p0;
            u.y = *(uint32_t*)&p1;
            *(uint2*)(op + i * 128 + lane * 4) = u;
        }
    }
    #pragma unroll
    for (int i = 0; i < 8; i++) *(float4*)(&sp[wid][i * 128 + lane * 4]) = pacc[i];
    __syncthreads();
    float* pp = partial + (long long)(b * 128 + ch) * HID;
    int h = threadIdx.x * 4;
    float4 s = make_float4(0.f, 0.f, 0.f, 0.f);
    #pragma unroll
    for (int w = 0; w < 8; w++) {
        float4 q = *(float4*)(&sp[w][h]);
        s.x += q.x; s.y += q.y; s.z += q.z; s.w += q.w;
    }
    *(float4*)(pp + h) = s;
}

// ---------------- 2. router (one block per batch) ----------------
__global__ void router_kernel(const float* __restrict__ partial,
                              const float* __restrict__ rw,
                              const float* __restrict__ rb,
                              float* __restrict__ probs) {
    __shared__ float red[3][32];
    const int b = blockIdx.x;
    const int h = threadIdx.x;
    const int wid = h >> 5, lid = h & 31;
    float s = 0.f;
    #pragma unroll 16
    for (int c = 0; c < 128; c++) s += partial[(long long)(b * 128 + c) * HID + h];
    float p = s * (1.0f / SEQ);
    float a0 = p * rw[h * NE + 0];
    float a1 = p * rw[h * NE + 1];
    float a2 = p * rw[h * NE + 2];
    #pragma unroll
    for (int o = 16; o > 0; o >>= 1) {
        a0 += __shfl_xor_sync(0xffffffffu, a0, o);
        a1 += __shfl_xor_sync(0xffffffffu, a1, o);
        a2 += __shfl_xor_sync(0xffffffffu, a2, o);
    }
    if (lid == 0) { red[0][wid] = a0; red[1][wid] = a1; red[2][wid] = a2; }
    __syncthreads();
    if (h == 0) {
        float l0 = rb[0], l1 = rb[1], l2 = rb[2];
        #pragma unroll
        for (int w = 0; w < 32; w++) { l0 += red[0][w]; l1 += red[1][w]; l2 += red[2][w]; }
        float mx = fmaxf(l0, fmaxf(l1, l2));
        float e0 = expf(l0 - mx), e1 = expf(l1 - mx), e2 = expf(l2 - mx);
        float inv = 1.0f / (e0 + e1 + e2);
        probs[b * 3 + 0] = e0 * inv;
        probs[b * 3 + 1] = e1 * inv;
        probs[b * 3 + 2] = e2 * inv;
    }
}

// ---------------- 3. fused mixing (half2 stores) ----------------
__device__ __forceinline__ void mixT_body(__half* __restrict__ dst,
                                          const float* __restrict__ src,
                                          const float* __restrict__ probs,
                                          int K, int N, int bx, int by, int tid, int perm) {
    __shared__ float t0[32][33], t1[32][33], t2[32][33];
    int tx = tid & 31, ty = tid >> 5;
    int k0 = by * 32, n0 = bx * 32;
    long long eSz = (long long)K * N;
    #pragma unroll
    for (int i = 0; i < 4; i++) {
        int k = k0 + ty + i * 8;
        long long o = (long long)k * N + n0 + tx;
        t0[ty + i * 8][tx] = src[o];
        t1[ty + i * 8][tx] = src[eSz + o];
        t2[ty + i * 8][tx] = src[2 * eSz + o];
    }
    __syncthreads();
    int kp = tid & 15;
    int nOff = tid >> 4;
    #pragma unroll
    for (int b = 0; b < NB; b++) {
        float p0 = probs[b * 3 + 0], p1 = probs[b * 3 + 1], p2 = probs[b * 3 + 2];
        #pragma unroll
        for (int i = 0; i < 2; i++) {
            int n = n0 + nOff + i * 16;
            int nl = nOff + i * 16;
            float va = p0 * t0[2 * kp][nl] + p1 * t1[2 * kp][nl] + p2 * t2[2 * kp][nl];
            float vb = p0 * t0[2 * kp + 1][nl] + p1 * t1[2 * kp + 1][nl] + p2 * t2[2 * kp + 1][nl];
            long long r = perm ? ((n < DI) ? 2 * n : 2 * (n - DI) + 1) : n;
            __half2 hv = __floats2half2_rn(va, vb);
            *(uint32_t*)(dst + (long long)b * eSz + r * K + k0 + 2 * kp) = *(uint32_t*)&hv;
        }
    }
}

__global__ void mix_all_kernel(__half* __restrict__ WiT, __half* __restrict__ WoT,
                               float* __restrict__ bi, float* __restrict__ bo,
                               const float* __restrict__ w_in, const float* __restrict__ w_out,
                               const float* __restrict__ b_in, const float* __restrict__ b_out,
                               const float* __restrict__ probs) {
    int bid = blockIdx.x, tid = threadIdx.x;
    if (bid < 2560) {
        mixT_body(WiT, w_in, probs, HID, D2, bid % 80, bid / 80, tid, 1);
    } else if (bid < 3840) {
        int id = bid - 2560;
        mixT_body(WoT, w_out, probs, DI, HID, id % 32, id / 32, tid, 0);
    } else if (bid < 3880) {
        int i = (bid - 3840) * 256 + tid;
        if (i < NB * D2) {
            int b = i / D2, j = i - b * D2;
            float v = probs[b * 3 + 0] * b_in[j] + probs[b * 3 + 1] * b_in[D2 + j] +
                      probs[b * 3 + 2] * b_in[2 * D2 + j];
            long long r = (j < DI) ? 2 * j : 2 * (j - DI) + 1;
            bi[(long long)b * D2 + r] = v;
        }
    } else {
        int i = (bid - 3880) * 256 + tid;
        if (i < NB * HID) {
            int b = i / HID, j = i - b * HID;
            bo[i] = probs[b * 3 + 0] * b_out[j] + probs[b * 3 + 1] * b_out[HID + j] +
                    probs[b * 3 + 2] * b_out[2 * HID + j];
        }
    }
}

// ---------------- 4/6. fp16 GEMM: mbarrier-decoupled cp.async 3-stage BK=64 ----------------
#define STAGE_BYTES 32768
#define MBAR_OFF (3 * STAGE_BYTES)

__global__ __launch_bounds__(256, 2) void hgemm_kernel(
    const __half* __restrict__ A, const __half* __restrict__ B,
    const float* __restrict__ bias, const float* __restrict__ resid,
    float* __restrict__ C, __half2* __restrict__ awOut,
    float* __restrict__ cA, float* __restrict__ cW, int K, int N,
    long long sA, long long sB, long long sC) {
    extern __shared__ uint8_t dsm[];
    const uint32_t smb = smem_u32(dsm);
    const uint32_t mb = smb + MBAR_OFF;
    const int tid = threadIdx.x;
    const int wid = tid >> 5;
    const int lane = tid & 31;
    const int bb = blockIdx.z;

    const __half* Abase = A + (long long)bb * sA + (long long)blockIdx.y * 128 * K;
    const __half* Bbase = B + (long long)bb * sB + (long long)blockIdx.x * 128 * K;

    const int g = lane >> 2, t = lane & 3;
    const int wm = wid >> 2;
    const int wn = wid & 3;

    float acc[4][4][4];
    #pragma unroll
    for (int i = 0; i < 4; i++)
        #pragma unroll
        for (int j = 0; j < 4; j++)
            #pragma unroll
            for (int q = 0; q < 4; q++) acc[i][j][q] = 0.f;

    const int KT = K >> 6;

    if (tid == 0) {
        #pragma unroll
        for (int s = 0; s < 3; s++) {
            mbar_init(mb + s * 16, 256);
            mbar_init(mb + s * 16 + 8, 256);
        }
    }
    __syncthreads();

    auto issue = [&](int kt, int stg) {
        uint32_t sb = smb + stg * STAGE_BYTES;
        #pragma unroll
        for (int u = 0; u < 4; u++) {
            int c = tid + u * 256;
            int row = c >> 3, k16 = c & 7;
            int phys = k16 ^ (row & 7);
            uint32_t off = row * 128 + phys * 16;
            cpa16(sb + off, Abase + (long long)row * K + kt * 64 + k16 * 8);
            cpa16(sb + 16384 + off, Bbase + (long long)row * K + kt * 64 + k16 * 8);
        }
    };

    #pragma unroll
    for (int k = 0; k < 3; k++) {
        issue(k, k);
        cpasync_mbar_arrive_noinc(mb + k * 16);
    }

    const int mi = lane >> 3;
    const int l7 = lane & 7;

    uint32_t cphBits = 0, pphBits = 0;
    int stC = 0;
    for (int kt = 0; kt < KT; kt++) {
        mbar_wait(mb + stC * 16, (cphBits >> stC) & 1u);
        cphBits ^= (1u << stC);

        uint32_t sa = smb + stC * STAGE_BYTES;
        uint32_t sbm = sa + 16384;
        #pragma unroll
        for (int ks = 0; ks < 4; ks++) {
            uint32_t af[4][4], bf[4][2];
            #pragma unroll
            for (int mf = 0; mf < 4; mf++) {
                int row = wm * 64 + mf * 16 + l7 + (mi & 1) * 8;
                int chunk = 2 * ks + (mi >> 1);
                int phys = chunk ^ (row & 7);
                ldsm_x4(af[mf][0], af[mf][1], af[mf][2], af[mf][3],
                        sa + row * 128 + phys * 16);
            }
            #pragma unroll
            for (int p = 0; p < 2; p++) {
                int row = wn * 32 + p * 16 + l7 + (mi >> 1) * 8;
                int chunk = 2 * ks + (mi & 1);
                int phys = chunk ^ (row & 7);
                uint32_t r0, r1, r2, r3;
                ldsm_x4(r0, r1, r2, r3, sbm + row * 128 + phys * 16);
                bf[2 * p][0] = r0; bf[2 * p][1] = r1;
                bf[2 * p + 1][0] = r2; bf[2 * p + 1][1] = r3;
            }
            #pragma unroll
            for (int mf = 0; mf < 4; mf++)
                #pragma unroll
                for (int nf = 0; nf < 4; nf++)
                    mma_f16(acc[mf][nf][0], acc[mf][nf][1], acc[mf][nf][2], acc[mf][nf][3],
                            af[mf][0], af[mf][1], af[mf][2], af[mf][3],
                            bf[nf][0], bf[nf][1]);
        }
        mbar_arrive(mb + stC * 16 + 8);

        if (kt + 3 < KT) {
            mbar_wait(mb + stC * 16 + 8, (pphBits >> stC) & 1u);
            pphBits ^= (1u << stC);
            issue(kt + 3, stC);
            cpasync_mbar_arrive_noinc(mb + stC * 16);
        }
        stC = (stC == 2) ? 0 : stC + 1;
    }

    const long long m0 = (long long)blockIdx.y * 128;
    const int n0 = blockIdx.x * 128;
    const float* bp = bias + (long long)bb * N + n0;

    if (awOut) {
        __syncthreads();
        uint32_t* sw = (uint32_t*)dsm;
        #pragma unroll
        for (int mf = 0; mf < 4; mf++) {
            int rl = (wm * 4 + mf) * 16 + g;
            #pragma unroll
            for (int nf = 0; nf < 4; nf++) {
                int col = (wn * 4 + nf) * 8 + 2 * t;
                float2 bv = *(const float2*)(bp + col);
                int dl = (wn * 4 + nf) * 4 + t;
                {
                    float hid = acc[mf][nf][0] + bv.x;
                    float gat = acc[mf][nf][1] + bv.y;
                    float z = __fdividef(1.f, 1.f + __expf(-gat));
                    float ht = (hid >= 0.f) ? (hid + 0.5f) : __fdividef(1.f, 1.f + __expf(-hid));
                    __half2 hv = __floats2half2_rn(1.0f - z, z * ht);
                    sw[rl * 65 + dl] = *(uint32_t*)&hv;
                }
                {
                    float hid = acc[mf][nf][2] + bv.x;
                    float gat = acc[mf][nf][3] + bv.y;
                    float z = __fdividef(1.f, 1.f + __expf(-gat));
                    float ht = (hid >= 0.f) ? (hid + 0.5f) : __fdividef(1.f, 1.f + __expf(-hid));
                    __half2 hv = __floats2half2_rn(1.0f - z, z * ht);
                    sw[(rl + 8) * 65 + dl] = *(uint32_t*)&hv;
                }
            }
        }
        __syncthreads();
        __half2* ap = awOut + (long long)bb * SEQ * DI;
        const int d0 = n0 >> 1;
        #pragma unroll
        for (int i = 0; i < 8; i++) {
            int lin = i * 256 + tid;
            int row = lin >> 4, c16 = lin & 15;
            uint4 u = make_uint4(sw[row * 65 + c16 * 4 + 0], sw[row * 65 + c16 * 4 + 1],
                                 sw[row * 65 + c16 * 4 + 2], sw[row * 65 + c16 * 4 + 3]);
            *(uint4*)(ap + (m0 + row) * DI + d0 + c16 * 4) = u;
        }
        // fused scan_a: chunk composite over the 128 rows of this tile
        {
            const int d = tid >> 2;
            const int q = tid & 3;
            float Acc = 1.f, Wcc = 0.f;
            #pragma unroll 8
            for (int i = 0; i < 32; i++) {
                uint32_t u = sw[(q * 32 + i) * 65 + d];
                __half2 hv = *(__half2*)&u;
                float a = __low2float(hv), w = __high2float(hv);
                Acc = a * Acc;
                Wcc = fmaf(a, Wcc, w);
            }
            const int base = lane & ~3;
            float Af = __shfl_sync(0xffffffffu, Acc, base);
            float Wf = __shfl_sync(0xffffffffu, Wcc, base);
            #pragma unroll
            for (int j = 1; j < 4; j++) {
                float Aj = __shfl_sync(0xffffffffu, Acc, base + j);
                float Wj = __shfl_sync(0xffffffffu, Wcc, base + j);
                Wf = fmaf(Aj, Wf, Wj);
                Af = Aj * Af;
            }
            if (q == 0) {
                int o = (bb * NCH + blockIdx.y) * DI + d0 + d;
                cA[o] = Af;
                cW[o] = Wf;
            }
        }
        return;
    }

    float* Cp = C + (long long)bb * sC;
    const float* Rp = resid ? (resid + (long long)bb * sC) : nullptr;
    #pragma unroll
    for (int mf = 0; mf < 4; mf++) {
        long long r0 = m0 + (wm * 4 + mf) * 16 + g;
        #pragma unroll
        for (int nf = 0; nf < 4; nf++) {
            int col = (wn * 4 + nf) * 8 + 2 * t;
            float2 bv = *(const float2*)(bp + col);
            long long o0 = r0 * N + n0 + col;
            long long o1 = (r0 + 8) * N + n0 + col;
            float2 v0 = make_float2(acc[mf][nf][0] + bv.x, acc[mf][nf][1] + bv.y);
            float2 v1 = make_float2(acc[mf][nf][2] + bv.x, acc[mf][nf][3] + bv.y);
            if (Rp) {
                float2 q0 = *(const float2*)(Rp + o0);
                float2 q1 = *(const float2*)(Rp + o1);
                v0.x += q0.x; v0.y += q0.y;
                v1.x += q1.x; v1.y += q1.y;
            }
            *(float2*)(Cp + o0) = v0;
            *(float2*)(Cp + o1) = v1;
        }
    }
}

// ---------------- 5. scan replay: inline prefix + double-buffered cp.async ----------------
__global__ __launch_bounds__(256) void scan_c_kernel(const __half2* __restrict__ aw,
                                                     const float* __restrict__ cA,
                                                     const float* __restrict__ cW,
                                                     __half* __restrict__ hsb,
                                                     float* __restrict__ ns,
                                                     float* __restrict__ auxp) {
    __shared__ uint32_t sa[2][16][256];   // 32 KB
    __shared__ __half sO[16][256];        // 8 KB
    int bid = blockIdx.x;
    if (bid == 0 && threadIdx.x == 0) *auxp = 0.0f;
    int b = bid / (5 * NCH);
    int rem = bid % (5 * NCH);
    int gA = rem / NCH, c = rem % NCH;
    int d0 = gA * 256;
    const int tid = threadIdx.x;

    const uint32_t* ab = (const uint32_t*)(aw + (long long)b * SEQ * DI);

    // issue tile t (16 rows) into buffer buf
    auto issue = [&](int s0, int buf) {
        #pragma unroll
        for (int i = 0; i < 4; i++) {
            int lin = i * 256 + tid;
            int row = lin >> 6;
            int c4 = (lin & 63) * 4;
            cpa16(smem_u32(&sa[buf][row][c4]), ab + (long long)(s0 + row) * DI + d0 + c4);
        }
    };

    // kick off tiles 0 and 1 before doing the prefix (overlap prefix with loads)
    issue(c * CH, 0);
    asm volatile("cp.async.commit_group;" ::: "memory");
    issue(c * CH + 16, 1);
    asm volatile("cp.async.commit_group;" ::: "memory");

    // inline prefix over chunk composites 0..c-1 (cA/cW L2-hot from GEMM1)
    float h = 0.f;
    {
        const float* pA = cA + (long long)b * NCH * DI + d0 + tid;
        const float* pW = cW + (long long)b * NCH * DI + d0 + tid;
        int j = 0;
        for (; j + 8 <= c; j += 8) {
            float a[8], w[8];
            #pragma unroll
            for (int u = 0; u < 8; u++) {
                a[u] = pA[(long long)(j + u) * DI];
                w[u] = pW[(long long)(j + u) * DI];
            }
            #pragma unroll
            for (int u = 0; u < 8; u++) h = fmaf(a[u], h, w[u]);
        }
        for (; j < c; j++)
            h = fmaf(pA[(long long)j * DI], h, pW[(long long)j * DI]);
    }

    __half* hb = hsb + (long long)b * SEQ * DI;
    const int T = CH / 16;   // 8 tiles
    for (int tt = 0; tt < T; tt++) {
        int s0 = c * CH + tt * 16;
        // wait for tile tt (keep 1 group in flight if one was issued after it)
        if (tt + 2 < T) {
            asm volatile("cp.async.wait_group 1;" ::: "memory");
        } else {
            asm volatile("cp.async.wait_group 0;" ::: "memory");
        }
        __syncthreads();
        int buf = tt & 1;
        // compute recurrence for this tile
        #pragma unroll
        for (int s = 0; s < 16; s++) {
            uint32_t u = sa[buf][s][tid];
            __half2 hv = *(__half2*)&u;
            h = fmaf(__low2float(hv), h, __high2float(hv));
            sO[s][tid] = __float2half(h);
        }
        __syncthreads();
        // issue tile tt+2 into this buffer (now fully consumed)
        if (tt + 2 < T) {
            issue(c * CH + (tt + 2) * 16, buf);
            asm volatile("cp.async.commit_group;" ::: "memory");
        }
        // coalesced store of this tile
        #pragma unroll
        for (int i = 0; i < 2; i++) {
            int lin = i * 256 + tid;
            int row = lin >> 5;
            int cc = (lin & 31) * 8;
            *(uint4*)(hb + (long long)(s0 + row) * DI + d0 + cc) = *(uint4*)&sO[row][cc];
        }
        __syncthreads();
    }
    if (c == NCH - 1) ns[b * DI + d0 + tid] = h;
}

// ---------------- launch ----------------
extern "C" void kernel_launch(void* const* d_in, const int* in_sizes, int n_in,
                              void* d_out, int out_size) {
    const float* inputs   = (const float*)d_in[0];
    const float* norm_w   = (const float*)d_in[1];
    const float* router_w = (const float*)d_in[2];
    const float* router_b = (const float*)d_in[3];
    const float* w_in     = (const float*)d_in[4];
    const float* b_in     = (const float*)d_in[5];
    const float* w_out    = (const float*)d_in[6];
    const float* b_out    = (const float*)d_in[7];
    float* out = (float*)d_out;

    __half *xnh, *WiT, *WoT, *hs;
    __half2* aw;
    float *partial, *probs, *bi, *bo, *cA, *cW;
    cudaGetSymbolAddress((void**)&xnh, g_xnh);
    cudaGetSymbolAddress((void**)&partial, g_partial);
    cudaGetSymbolAddress((void**)&probs, g_probs);
    cudaGetSymbolAddress((void**)&WiT, g_WiT);
    cudaGetSymbolAddress((void**)&bi, g_bi);
    cudaGetSymbolAddress((void**)&WoT, g_WoT);
    cudaGetSymbolAddress((void**)&bo, g_bo);
    cudaGetSymbolAddress((void**)&aw, g_aw);
    cudaGetSymbolAddress((void**)&hs, g_hs);
    cudaGetSymbolAddress((void**)&cA, g_cA);
    cudaGetSymbolAddress((void**)&cW, g_cW);

    const int DYN = 3 * STAGE_BYTES + 64;
    cudaFuncSetAttribute(hgemm_kernel, cudaFuncAttributeMaxDynamicSharedMemorySize, DYN);

    norm_pool_kernel<<<NB * 128, 256>>>(inputs, norm_w, xnh, partial);
    router_kernel<<<NB, 1024>>>(partial, router_w, router_b, probs);
    mix_all_kernel<<<3896, 256>>>(WiT, WoT, bi, bo, w_in, w_out, b_in, b_out, probs);
    {   // GEMM1 -> aw pairs + fused chunk composites (4th launch: profiled)
        dim3 grid(D2 / 128, SEQ / 128, NB);
        hgemm_kernel<<<grid, 256, DYN>>>(xnh, WiT, bi, nullptr, nullptr, aw, cA, cW, HID, D2,
                                         (long long)SEQ * HID, (long long)HID * D2, 0);
    }
    scan_c_kernel<<<NB * 5 * NCH, 256>>>(aw, cA, cW, hs,
                                         out + (long long)NB * SEQ * HID,
                                         out + (long long)out_size - 1);
    {   // GEMM2: out = hs @ WoT^T + bo + inputs
        dim3 grid(HID / 128, SEQ / 128, NB);
        hgemm_kernel<<<grid, 256, DYN>>>(hs, WoT, bo, inputs, out, nullptr, nullptr, nullptr,
                                         DI, HID,
                                         (long long)SEQ * DI, (long long)DI * HID,
                                         (long long)SEQ * HID);
    }
}